// round 7
// baseline (speedup 1.0000x reference)
#include <cuda_runtime.h>
#include <math.h>

// VQ on GB300 via legacy tensor-core path (mma.sync tf32, plain sm_103 target)
// + certified exact fp32 rescore for bit-exact argmins.
#define C_DIM 128
#define HW 4096
#define BN 64
#define N_TILES 4096
#define NTH 256
#define GRID 148
#define NQ 33554432
#define N_TOT 262144

// smem byte offsets
#define AP_OFF 0          // emb fragment-perm: 256k x 128c f32 (131072)
#define BP_OFF 131072     // z fragment-perm: 128c x 64n f32 (32768)
#define SE_OFF 163840     // se[256]
#define APT_OFF 164864    // Ap[256]
#define AN_OFF 165888     // An[64] (256B pad)
#define WMIN_OFF 166144   // wmin[4][64]
#define THR_OFF 167168    // thr[64] (256B)
#define CNT_OFF 167424    // cnt[64]
#define CAND_OFF 167680   // cand[64][16] int
#define IDX_OFF 171776    // idx_s[64] (256B)
#define WS_OFF 172032     // wsum[8] + semax
#define SMEM_BYTES 172096

__device__ double d_loss_sum;

__device__ __forceinline__ void mma8(float* d, uint4 a, uint2 b){
    asm volatile("mma.sync.aligned.m16n8k8.row.col.f32.tf32.tf32.f32 "
        "{%0,%1,%2,%3},{%4,%5,%6,%7},{%8,%9},{%0,%1,%2,%3};"
        : "+f"(d[0]),"+f"(d[1]),"+f"(d[2]),"+f"(d[3])
        : "r"(a.x),"r"(a.y),"r"(a.z),"r"(a.w),"r"(b.x),"r"(b.y));
}
// fragment-perm float indices
__device__ __forceinline__ int aidx(int k,int c){   // emb element (code k, chan c)
    return ((c>>3)*16 + (k>>4))*128 + ((k&7)*4 + (c&3))*4 + ((k>>3)&1) + 2*((c>>2)&1);
}
__device__ __forceinline__ int bidx(int c,int n){   // z element (chan c, query n)
    return ((c>>3)*8 + (n>>3))*64 + ((n&7)*4 + (c&3))*2 + ((c>>2)&1);
}
// exact reference-semantics distance (identical to R3-passing formula)
__device__ __forceinline__ float exact_d(const float* BP, const float* __restrict__ emb,
                                         float A, float sek, int n, int k){
    float g=0.f;
    #pragma unroll 8
    for(int c=0;c<C_DIM;++c){
        float zv=BP[bidx(c,n)];
        float ev=__ldg(emb+k*C_DIM+c);
        g=__fmaf_rn(zv,ev,g);
    }
    return __fadd_rn(__fadd_rn(A,-__fmul_rn(2.0f,g)),sek);
}
__device__ __forceinline__ unsigned fkey(float d){
    unsigned u=__float_as_uint(d); return ((int)u<0)?~u:(u|0x80000000u);
}

__global__ void vq_zero(){ d_loss_sum=0.0; }

__global__ void __launch_bounds__(NTH,1)
vq_main(const float* __restrict__ z, const float* __restrict__ emb,
        float* __restrict__ out_q, float* __restrict__ out_idx){
    extern __shared__ char sm[];
    float* AP=(float*)(sm+AP_OFF);
    float* BP=(float*)(sm+BP_OFF);
    float* se=(float*)(sm+SE_OFF);
    float* Ap=(float*)(sm+APT_OFF);
    float* An=(float*)(sm+AN_OFF);
    float* wmin=(float*)(sm+WMIN_OFF);
    float* thr=(float*)(sm+THR_OFF);
    int* cnt=(int*)(sm+CNT_OFF);
    int* cand=(int*)(sm+CAND_OFF);
    int* idx_s=(int*)(sm+IDX_OFF);
    float* wsum=(float*)(sm+WS_OFF);

    const int tid=threadIdx.x, lane=tid&31, w=tid>>5;
    const int wm=w&3, wn=w>>2, g=lane>>2, tig=lane&3;

    // ---- prologue: stage emb into fragment-perm layout + se chain ----
    {
        int k=tid;
        const float4* er=(const float4*)(emb+(size_t)k*C_DIM);
        float s=0.f;
        #pragma unroll 8
        for(int i=0;i<32;++i){
            float4 v=er[i]; int c=i*4;
            AP[aidx(k,c)]=v.x;   AP[aidx(k,c+1)]=v.y;
            AP[aidx(k,c+2)]=v.z; AP[aidx(k,c+3)]=v.w;
            s=__fmaf_rn(v.x,v.x,s); s=__fmaf_rn(v.y,v.y,s);
            s=__fmaf_rn(v.z,v.z,s); s=__fmaf_rn(v.w,v.w,s);
        }
        se[k]=s;
    }
    __syncthreads();
    if(w==0){
        float m=se[lane];
        #pragma unroll
        for(int i=1;i<8;++i) m=fmaxf(m,se[lane+i*32]);
        #pragma unroll
        for(int o=16;o>0;o>>=1) m=fmaxf(m,__shfl_xor_sync(0xFFFFFFFFu,m,o));
        if(lane==0) wsum[8]=m;
    }
    __syncthreads();
    const float semax=wsum[8];

    float lsum=0.f;
    for(int tile=blockIdx.x; tile<N_TILES; tile+=GRID){
        const int b=tile>>6, hw0=(tile&63)<<6;
        const float* zb=z+(size_t)b*(C_DIM*HW)+hw0;

        // ---- stage z tile into fragment-perm ----
        #pragma unroll
        for(int i=0;i<8;++i){
            int idx=tid+i*NTH;            // 2048 float4
            int c=idx>>4, n4=(idx&15)<<2;
            float4 v=*(const float4*)(zb+(size_t)c*HW+n4);
            BP[bidx(c,n4)]=v.x;   BP[bidx(c,n4+1)]=v.y;
            BP[bidx(c,n4+2)]=v.z; BP[bidx(c,n4+3)]=v.w;
        }
        __syncthreads();

        // ---- A_n partial chains (order argmin-invariant) ----
        {
            int n=tid&63, part=tid>>6;
            float a=0.f;
            #pragma unroll 8
            for(int j=0;j<32;++j){
                float v=BP[bidx(part*32+j,n)];
                a=__fmaf_rn(v,v,a);
            }
            Ap[tid]=a;
        }
        __syncthreads();
        if(tid<64) An[tid]=((Ap[tid]+Ap[64+tid])+Ap[128+tid])+Ap[192+tid];

        // ---- tensor mainloop: 16 k-steps, 4x4 m16n8k8 per warp ----
        float acc[4][4][4];
        #pragma unroll
        for(int j=0;j<4;++j)
            #pragma unroll
            for(int i=0;i<4;++i)
                #pragma unroll
                for(int e=0;e<4;++e) acc[j][i][e]=0.f;
        {
            const uint4* AP4=(const uint4*)AP;
            const uint2* BP2=(const uint2*)BP;
            #pragma unroll 4
            for(int ks=0;ks<16;++ks){
                uint4 a[4]; uint2 bb[4];
                #pragma unroll
                for(int j=0;j<4;++j) a[j]=AP4[(ks*16+wm*4+j)*32+lane];
                #pragma unroll
                for(int i=0;i<4;++i) bb[i]=BP2[(ks*8+wn*4+i)*32+lane];
                #pragma unroll
                for(int j=0;j<4;++j)
                    #pragma unroll
                    for(int i=0;i<4;++i) mma8(acc[j][i],a[j],bb[i]);
            }
        }

        // ---- approx scores, per-column mins, warp+block reduce ----
        float seR[4][2];
        #pragma unroll
        for(int j=0;j<4;++j){
            seR[j][0]=se[wm*64+j*16+g];
            seR[j][1]=se[wm*64+j*16+g+8];
        }
        float lm[4][2];
        #pragma unroll
        for(int i=0;i<4;++i)
            #pragma unroll
            for(int p=0;p<2;++p){
                float m=1e30f;
                #pragma unroll
                for(int j=0;j<4;++j)
                    #pragma unroll
                    for(int r=0;r<2;++r){
                        float s=__fmaf_rn(-2.f,acc[j][i][r*2+p],seR[j][r]);
                        m=fminf(m,s);
                    }
                lm[i][p]=m;
            }
        #pragma unroll
        for(int o=4;o<32;o<<=1)
            #pragma unroll
            for(int i=0;i<4;++i)
                #pragma unroll
                for(int p=0;p<2;++p)
                    lm[i][p]=fminf(lm[i][p],__shfl_xor_sync(0xFFFFFFFFu,lm[i][p],o));
        if(g==0){
            #pragma unroll
            for(int i=0;i<4;++i)
                #pragma unroll
                for(int p=0;p<2;++p)
                    wmin[wm*64+wn*32+i*8+2*tig+p]=lm[i][p];
        }
        __syncthreads();
        if(tid<64){
            float m=fminf(fminf(wmin[tid],wmin[64+tid]),fminf(wmin[128+tid],wmin[192+tid]));
            thr[tid]=m+(0.0078125f*sqrtf(An[tid]*semax)+2e-4f);
            cnt[tid]=0;
        }
        __syncthreads();

        // ---- candidate collection within certified window ----
        #pragma unroll
        for(int i=0;i<4;++i)
            #pragma unroll
            for(int p=0;p<2;++p){
                int q=wn*32+i*8+2*tig+p;
                float t=thr[q];
                #pragma unroll
                for(int j=0;j<4;++j)
                    #pragma unroll
                    for(int r=0;r<2;++r){
                        float s=__fmaf_rn(-2.f,acc[j][i][r*2+p],seR[j][r]);
                        if(s<=t){
                            int slot=atomicAdd(&cnt[q],1);
                            if(slot<16) cand[q*16+slot]=wm*64+j*16+g+8*r;
                        }
                    }
            }
        __syncthreads();

        // ---- exact rescore (bit-exact reference semantics) ----
        if(tid<64){
            int q=tid, m=cnt[q], kbest;
            float A=An[q];
            if(m==1){ kbest=cand[q*16]; }
            else if(m<=16){
                unsigned long long best=~0ull;
                for(int i=0;i<m;++i){
                    int k=cand[q*16+i];
                    float d=exact_d(BP,emb,A,se[k],q,k);
                    unsigned long long key=((unsigned long long)fkey(d)<<32)|(unsigned)k;
                    if(key<best) best=key;
                }
                kbest=(int)(best&255u);
            } else {
                unsigned long long best=~0ull;
                for(int k=0;k<256;++k){
                    float d=exact_d(BP,emb,A,se[k],q,k);
                    unsigned long long key=((unsigned long long)fkey(d)<<32)|(unsigned)k;
                    if(key<best) best=key;
                }
                kbest=(int)(best&255u);
            }
            idx_s[q]=kbest;
        }
        __syncthreads();

        // ---- epilogue: reference fp ops; z re-read from gmem (L2-hot) ----
        {
            float* outb=out_q+(size_t)b*(C_DIM*HW)+hw0;
            #pragma unroll
            for(int i=0;i<8;++i){
                int idx=tid+i*NTH;
                int c=idx>>4, n4=(idx&15)<<2;
                float4 zv=*(const float4*)(zb+(size_t)c*HW+n4);
                int k0=idx_s[n4],k1=idx_s[n4+1],k2=idx_s[n4+2],k3=idx_s[n4+3];
                float q0=__ldg(emb+k0*C_DIM+c), q1=__ldg(emb+k1*C_DIM+c);
                float q2=__ldg(emb+k2*C_DIM+c), q3=__ldg(emb+k3*C_DIM+c);
                float d0=q0-zv.x,d1=q1-zv.y,d2=q2-zv.z,d3=q3-zv.w;
                lsum=__fmaf_rn(d0,d0,lsum); lsum=__fmaf_rn(d1,d1,lsum);
                lsum=__fmaf_rn(d2,d2,lsum); lsum=__fmaf_rn(d3,d3,lsum);
                float4 o=make_float4(zv.x+d0,zv.y+d1,zv.z+d2,zv.w+d3);
                *(float4*)(outb+(size_t)c*HW+n4)=o;
            }
            if(out_idx!=nullptr && tid<64)
                out_idx[(size_t)tile*BN+tid]=(float)idx_s[tid];
        }
        __syncthreads();
    }

    // ---- loss reduce -> double atomic ----
    #pragma unroll
    for(int o=16;o>0;o>>=1) lsum+=__shfl_xor_sync(0xFFFFFFFFu,lsum,o);
    if(lane==0) wsum[w]=lsum;
    __syncthreads();
    if(tid==0){
        float t=0.f;
        #pragma unroll
        for(int i=0;i<8;++i) t+=wsum[i];
        atomicAdd(&d_loss_sum,(double)t);
    }
}

__global__ void vq_finalize(float* out_s){
    double mse=d_loss_sum*(1.0/(double)NQ);
    out_s[0]=(float)(0.25*mse);
    out_s[1]=(float)mse;
}

extern "C" void kernel_launch(void* const* d_in, const int* in_sizes, int n_in,
                              void* d_out, int out_size){
    const float *z,*emb;
    if(n_in>=2 && in_sizes[0]==256*C_DIM){ emb=(const float*)d_in[0]; z=(const float*)d_in[1]; }
    else { z=(const float*)d_in[0]; emb=(const float*)d_in[1]; }
    float* out=(float*)d_out;
    cudaFuncSetAttribute(vq_main, cudaFuncAttributeMaxDynamicSharedMemorySize, SMEM_BYTES);
    float* out_idx=nullptr; float* out_s=nullptr;
    long long osz=(long long)out_size;
    if(osz>=(long long)NQ+N_TOT) out_idx=out+NQ;
    if(osz>=(long long)NQ+N_TOT+2) out_s=out+NQ+N_TOT;
    vq_zero<<<1,1>>>();
    vq_main<<<GRID,NTH,SMEM_BYTES>>>(z,emb,out,out_idx);
    if(out_s) vq_finalize<<<1,1>>>(out_s);
}